// round 1
// baseline (speedup 1.0000x reference)
#include <cuda_runtime.h>
#include <cuda_bf16.h>

// RoiPoolingConv: crop + bilinear resize (tf.image.resize_images,
// align_corners=False: src = dst * in/out, edge-clamped).
// img:  [1, 128, 128, 512] float32 (NHWC)
// rois: [1000, 4] int32  (x1, y1, x2, y2), SCALE=1.0
// out:  [1000, 14, 14, 512] float32
//
// Layout: one block per (roi, py). 128 threads, each owns one float4
// (4 channels) of the 512-channel vector. Loop over px = 0..13.
// Both bilinear source rows (yt, yb) are fixed per block, so the 14 px
// iterations re-read the same two image rows at overlapping columns —
// L1 catches that reuse; L2 only sees the unique row segments.

#define PH 14
#define PW 14
#define IMG_W 128
#define NCH 512
#define NV4 (NCH / 4)   // 128 float4 per pixel

__global__ __launch_bounds__(NV4, 8)
void roi_pool_kernel(const float4* __restrict__ img,
                     const int4* __restrict__ rois,
                     float4* __restrict__ out) {
    const int py = blockIdx.x;     // 0..13
    const int n  = blockIdx.y;     // roi index
    const int t  = threadIdx.x;    // 0..127 (float4 lane)

    const int4 r = rois[n];
    const int x0 = r.x;
    const int y0 = r.y;
    const int in_w = r.z - r.x + 1;
    const int in_h = r.w - r.y + 1;

    // Match reference float order: sy = py * (in_h / PH)
    const float fy = (float)py * ((float)in_h / (float)PH);
    const int yt = (int)floorf(fy);
    const int yb = min(yt + 1, in_h - 1);
    const float wy = fy - (float)yt;

    const int rowT = (y0 + yt) * IMG_W;
    const int rowB = (y0 + yb) * IMG_W;
    const float sxw = (float)in_w / (float)PW;

    float4* outp = out + (((size_t)n * PH + py) * PW) * NV4 + t;

    #pragma unroll
    for (int px = 0; px < PW; ++px) {
        const float fx = (float)px * sxw;
        const int xt = (int)floorf(fx);
        const int xr = min(xt + 1, in_w - 1);
        const float wx = fx - (float)xt;
        const int cl = x0 + xt;
        const int cr = x0 + xr;

        const float4 v00 = __ldg(img + (size_t)(rowT + cl) * NV4 + t);
        const float4 v01 = __ldg(img + (size_t)(rowT + cr) * NV4 + t);
        const float4 v10 = __ldg(img + (size_t)(rowB + cl) * NV4 + t);
        const float4 v11 = __ldg(img + (size_t)(rowB + cr) * NV4 + t);

        float4 o;
        {
            float top, bot;
            top = v00.x + wx * (v01.x - v00.x);
            bot = v10.x + wx * (v11.x - v10.x);
            o.x = top + wy * (bot - top);
            top = v00.y + wx * (v01.y - v00.y);
            bot = v10.y + wx * (v11.y - v10.y);
            o.y = top + wy * (bot - top);
            top = v00.z + wx * (v01.z - v00.z);
            bot = v10.z + wx * (v11.z - v10.z);
            o.z = top + wy * (bot - top);
            top = v00.w + wx * (v01.w - v00.w);
            bot = v10.w + wx * (v11.w - v10.w);
            o.w = top + wy * (bot - top);
        }
        outp[(size_t)px * NV4] = o;
    }
}

extern "C" void kernel_launch(void* const* d_in, const int* in_sizes, int n_in,
                              void* d_out, int out_size) {
    const float4* img  = (const float4*)d_in[0];
    const int4*   rois = (const int4*)d_in[1];
    float4*       out  = (float4*)d_out;

    const int n_rois = in_sizes[1] / 4;   // 1000

    dim3 grid(PH, n_rois);
    dim3 block(NV4);
    roi_pool_kernel<<<grid, block>>>(img, rois, out);
}